// round 13
// baseline (speedup 1.0000x reference)
#include <cuda_runtime.h>
#include <cstdint>
#include <math.h>

#define N_BATCH 32
#define C_IN    256
#define C_SQ    64
#define HW      12544              // floats per plane (112*112)
#define HW4     3136               // float4 per plane = 448*7
#define TPB     448
#define VPT     7                  // float4 per thread per plane
#define NBLK    256                // one channel per block; 256 <= 296 resident
#define SMEM_BYTES (2 * HW * 4)    // two plane buffers: 100352 B

// Scratch (no allocations). Zero-initialized; self-resetting per replay.
__device__ float    g_pool[N_BATCH * C_IN];
__device__ float    g_gate[N_BATCH * C_IN];
__device__ unsigned g_cnt [N_BATCH];
__device__ unsigned g_done[N_BATCH];
__device__ unsigned g_cnt2[N_BATCH];

__device__ __forceinline__ unsigned ld_acquire_gpu(const unsigned* p) {
    unsigned v;
    asm volatile("ld.acquire.gpu.u32 %0, [%1];" : "=r"(v) : "l"(p) : "memory");
    return v;
}
__device__ __forceinline__ unsigned int smem_u32(const void* p) {
    return (unsigned int)__cvta_generic_to_shared(p);
}
__device__ __forceinline__ void cp_async16(unsigned int dst, const void* src) {
    asm volatile("cp.async.cg.shared.global [%0], [%1], 16;"
                 :: "r"(dst), "l"(src) : "memory");
}
__device__ __forceinline__ void cp_commit() {
    asm volatile("cp.async.commit_group;" ::: "memory");
}
template <int N> __device__ __forceinline__ void cp_wait() {
    asm volatile("cp.async.wait_group %0;" :: "n"(N) : "memory");
}

// ---------------------------------------------------------------------------
// Persistent pipelined SE kernel: x is read from DRAM exactly once.
// Block b owns channel c=b for every batch. Per batch: cp.async plane into
// SMEM (double-buffered, prefetched one batch ahead), reduce, batch-wide
// counter, last-arriver computes the MLP, everyone scales from SMEM.
// ---------------------------------------------------------------------------
__global__ __launch_bounds__(TPB, 2) void se_pipe_kernel(
    const float* __restrict__ x,
    float*       __restrict__ out,
    const float* __restrict__ w_reduce,   // [C_SQ, C_IN]
    const float* __restrict__ b_reduce,   // [C_SQ]
    const float* __restrict__ w_expand,   // [C_IN, C_SQ]
    const float* __restrict__ b_expand)   // [C_IN]
{
    extern __shared__ float smem[];                 // 2 plane buffers
    __shared__ float warp_partial[TPB / 32];        // 14
    __shared__ float s_in[C_IN];
    __shared__ float s_red[C_SQ];
    __shared__ int   s_last;

    const int c    = blockIdx.x;                    // channel 0..255
    const int tid  = threadIdx.x;
    const int lane = tid & 31;
    const int wid  = tid >> 5;

    // ---- prologue: prefetch batch 0's plane into buffer 0 ----
    {
        const float4* src = reinterpret_cast<const float4*>(x + (size_t)c * HW);
        unsigned int dst = smem_u32(smem);
        #pragma unroll
        for (int i = 0; i < VPT; i++)
            cp_async16(dst + (unsigned int)(tid + i * TPB) * 16u, src + tid + i * TPB);
        cp_commit();
    }

    for (int n = 0; n < N_BATCH; n++) {
        float* cur = smem + (n & 1) * HW;

        // ---- prefetch batch n+1 into the other buffer, then wait for n ----
        if (n + 1 < N_BATCH) {
            const float4* src = reinterpret_cast<const float4*>(
                x + ((size_t)(n + 1) * C_IN + c) * HW);
            unsigned int dst = smem_u32(smem + ((n + 1) & 1) * HW);
            #pragma unroll
            for (int i = 0; i < VPT; i++)
                cp_async16(dst + (unsigned int)(tid + i * TPB) * 16u, src + tid + i * TPB);
            cp_commit();
            cp_wait<1>();                    // batch n's group complete
        } else {
            cp_wait<0>();
        }
        __syncthreads();

        // ---- reduce this plane -> mean ----
        const float4* cv = reinterpret_cast<const float4*>(cur);
        float sum = 0.0f;
        #pragma unroll
        for (int i = 0; i < VPT; i++) {
            float4 v = cv[tid + i * TPB];
            sum += (v.x + v.y) + (v.z + v.w);
        }
        #pragma unroll
        for (int off = 16; off > 0; off >>= 1)
            sum += __shfl_down_sync(0xFFFFFFFFu, sum, off);
        if (lane == 0) warp_partial[wid] = sum;
        __syncthreads();

        if (tid == 0) {
            float s = 0.0f;
            #pragma unroll
            for (int w = 0; w < TPB / 32; w++) s += warp_partial[w];
            g_pool[n * C_IN + c] = s * (1.0f / (float)HW);
            __threadfence();                                  // release mean
            unsigned old = atomicAdd(&g_cnt[n], 1u);
            s_last = (old == (unsigned)(NBLK - 1));
        }
        __syncthreads();

        // ---- last arriver computes the whole MLP for batch n ----
        if (s_last) {
            if (tid < C_IN) s_in[tid] = __ldcg(&g_pool[n * C_IN + tid]);
            __syncthreads();
            if (tid < C_SQ) {
                float a0 = b_reduce[tid], a1 = 0.f, a2 = 0.f, a3 = 0.f;
                const float* wr = w_reduce + tid * C_IN;
                #pragma unroll 4
                for (int k = 0; k < C_IN; k += 4) {
                    a0 = fmaf(wr[k + 0], s_in[k + 0], a0);
                    a1 = fmaf(wr[k + 1], s_in[k + 1], a1);
                    a2 = fmaf(wr[k + 2], s_in[k + 2], a2);
                    a3 = fmaf(wr[k + 3], s_in[k + 3], a3);
                }
                s_red[tid] = fmaxf((a0 + a1) + (a2 + a3), 0.0f);
            }
            __syncthreads();
            if (tid < C_IN) {
                float acc = b_expand[tid];
                const float* we = w_expand + tid * C_SQ;
                #pragma unroll 8
                for (int k = 0; k < C_SQ; k++)
                    acc = fmaf(we[k], s_red[k], acc);
                g_gate[n * C_IN + tid] = 1.0f / (1.0f + __expf(-acc));
            }
            __syncthreads();
            if (tid == 0) {
                __threadfence();                              // release gates
                atomicExch(&g_done[n], 1u);
            }
        }

        // ---- wait for gates (prefetch of n+1 keeps DRAM busy meanwhile) ----
        if (tid == 0) {
            while (ld_acquire_gpu(&g_done[n]) == 0u)
                __nanosleep(32);
        }
        __syncthreads();

        const float g = __ldcg(&g_gate[n * C_IN + c]);

        // ---- scale from SMEM and stream out ----
        float4* q = reinterpret_cast<float4*>(out + ((size_t)n * C_IN + c) * HW);
        #pragma unroll
        for (int i = 0; i < VPT; i++) {
            float4 v = cv[tid + i * TPB];
            v.x *= g; v.y *= g; v.z *= g; v.w *= g;
            __stcs(&q[tid + i * TPB], v);
        }

        // ---- self-reset bookkeeping once all blocks passed the spin ----
        if (tid == 0) {
            unsigned old2 = atomicAdd(&g_cnt2[n], 1u);
            if (old2 == (unsigned)(NBLK - 1)) {
                atomicExch(&g_cnt [n], 0u);
                atomicExch(&g_done[n], 0u);
                atomicExch(&g_cnt2[n], 0u);
            }
        }
        __syncthreads();     // nobody overwrites cur's sibling buffer early
    }
}

// ---------------------------------------------------------------------------
extern "C" void kernel_launch(void* const* d_in, const int* in_sizes, int n_in,
                              void* d_out, int out_size)
{
    const float* x        = (const float*)d_in[0];
    const float* w_reduce = (const float*)d_in[1];
    const float* b_reduce = (const float*)d_in[2];
    const float* w_expand = (const float*)d_in[3];
    const float* b_expand = (const float*)d_in[4];
    float* out = (float*)d_out;

    static int configured = 0;
    if (!configured) {
        cudaFuncSetAttribute(se_pipe_kernel,
                             cudaFuncAttributeMaxDynamicSharedMemorySize,
                             SMEM_BYTES);
        configured = 1;
    }

    se_pipe_kernel<<<NBLK, TPB, SMEM_BYTES>>>(x, out, w_reduce, b_reduce,
                                              w_expand, b_expand);
}

// round 14
// speedup vs baseline: 3.9156x; 3.9156x over previous
#include <cuda_runtime.h>
#include <math.h>

#define N_BATCH 32
#define C_IN    256
#define C_SQ    64
#define HW      12544              // 112*112
#define HW4     3136               // HW/4 float4 per plane
#define PLANES  (N_BATCH * C_IN)   // 8192
#define TPB     448                // 448 * 7 == 3136 exactly
#define VPT     7                  // float4 per thread (scale kernel)

// Scratch (no allocations allowed)
__device__ float g_pool[PLANES];
__device__ float g_gate[PLANES];

// ---------------------------------------------------------------------------
// Kernel 1: global average pool. One block per (n,c) plane, 256 threads,
// strided float4 loop. Early PDL trigger right after the result store.
// ---------------------------------------------------------------------------
__global__ __launch_bounds__(256) void se_pool_kernel(
    const float* __restrict__ x)
{
    const int plane = blockIdx.x;
    const float4* p = reinterpret_cast<const float4*>(x + (size_t)plane * HW);

    float sum = 0.0f;
    #pragma unroll 4
    for (int i = threadIdx.x; i < HW4; i += 256) {
        float4 v = p[i];
        sum += (v.x + v.y) + (v.z + v.w);
    }

    #pragma unroll
    for (int off = 16; off > 0; off >>= 1)
        sum += __shfl_down_sync(0xFFFFFFFFu, sum, off);

    __shared__ float warp_sums[8];
    const int lane = threadIdx.x & 31;
    const int wid  = threadIdx.x >> 5;
    if (lane == 0) warp_sums[wid] = sum;
    __syncthreads();

    if (wid == 0) {
        float s = (lane < 8) ? warp_sums[lane] : 0.0f;
        #pragma unroll
        for (int off = 4; off > 0; off >>= 1)
            s += __shfl_down_sync(0xFFFFFFFFu, s, off);
        if (lane == 0)
            g_pool[plane] = s * (1.0f / (float)HW);
    }
    cudaTriggerProgrammaticLaunchCompletion();
}

// ---------------------------------------------------------------------------
// Kernel 2: MLP. PDL secondary: launches during pool's drain, waits on pool
// results via cudaGridDependencySynchronize, triggers early for scale.
// ---------------------------------------------------------------------------
__global__ __launch_bounds__(256) void se_mlp_kernel(
    const float* __restrict__ w_reduce,   // [C_SQ, C_IN]
    const float* __restrict__ b_reduce,   // [C_SQ]
    const float* __restrict__ w_expand,   // [C_IN, C_SQ]
    const float* __restrict__ b_expand)   // [C_IN]
{
    const int n   = blockIdx.x;
    const int tid = threadIdx.x;

    __shared__ float s_in[C_IN];
    __shared__ float s_red[C_SQ];

    cudaGridDependencySynchronize();      // pool results now visible

    s_in[tid] = g_pool[n * C_IN + tid];
    __syncthreads();

    if (tid < C_SQ) {
        float acc = b_reduce[tid];
        const float* wr = w_reduce + tid * C_IN;
        #pragma unroll 8
        for (int c = 0; c < C_IN; c++)
            acc = fmaf(wr[c], s_in[c], acc);
        s_red[tid] = fmaxf(acc, 0.0f);
    }
    __syncthreads();

    float acc = b_expand[tid];
    const float* we = w_expand + tid * C_SQ;
    #pragma unroll 8
    for (int k = 0; k < C_SQ; k++)
        acc = fmaf(we[k], s_red[k], acc);

    g_gate[n * C_IN + tid] = 1.0f / (1.0f + __expf(-acc));

    cudaTriggerProgrammaticLaunchCompletion();
}

// ---------------------------------------------------------------------------
// Kernel 3: out = gate[plane] * x. PDL secondary: front-batch the 7 x-plane
// loads BEFORE cudaGridDependencySynchronize (x is a kernel input, not a
// product of pool/mlp), so the load ramp overlaps the previous grids' drain.
// Reversed plane order for L2 tail reuse; streaming stores.
// ---------------------------------------------------------------------------
__global__ __launch_bounds__(TPB) void se_scale_kernel(
    const float* __restrict__ x,
    float*       __restrict__ out)
{
    const int plane = (PLANES - 1) - blockIdx.x;

    const float4* p = reinterpret_cast<const float4*>(x   + (size_t)plane * HW);
    float4*       q = reinterpret_cast<float4*>(out       + (size_t)plane * HW);

    float4 v[VPT];
    #pragma unroll
    for (int i = 0; i < VPT; i++)
        v[i] = p[threadIdx.x + i * TPB];

    cudaGridDependencySynchronize();      // gates now guaranteed visible

    const float g = __ldg(&g_gate[plane]);

    #pragma unroll
    for (int i = 0; i < VPT; i++) {
        v[i].x *= g; v[i].y *= g; v[i].z *= g; v[i].w *= g;
        __stcs(&q[threadIdx.x + i * TPB], v[i]);
    }
}

// ---------------------------------------------------------------------------
static void launch_pdl(void* fn, dim3 grid, dim3 block,
                       void** args)
{
    cudaLaunchConfig_t cfg = {};
    cfg.gridDim  = grid;
    cfg.blockDim = block;
    cfg.stream   = 0;
    cudaLaunchAttribute attr[1];
    attr[0].id = cudaLaunchAttributeProgrammaticStreamSerialization;
    attr[0].val.programmaticStreamSerializationAllowed = 1;
    cfg.attrs    = attr;
    cfg.numAttrs = 1;
    cudaLaunchKernelExC(&cfg, fn, args);
}

extern "C" void kernel_launch(void* const* d_in, const int* in_sizes, int n_in,
                              void* d_out, int out_size)
{
    const float* x        = (const float*)d_in[0];
    const float* w_reduce = (const float*)d_in[1];
    const float* b_reduce = (const float*)d_in[2];
    const float* w_expand = (const float*)d_in[3];
    const float* b_expand = (const float*)d_in[4];
    float* out = (float*)d_out;

    // Pool: normal launch
    se_pool_kernel<<<PLANES, 256>>>(x);

    // MLP: PDL secondary (launch overlaps pool drain)
    {
        void* args[] = { (void*)&w_reduce, (void*)&b_reduce,
                         (void*)&w_expand, (void*)&b_expand };
        launch_pdl((void*)se_mlp_kernel, dim3(N_BATCH), dim3(256), args);
    }

    // Scale: PDL secondary (launch/load ramp overlaps mlp + pool drain)
    {
        void* args[] = { (void*)&x, (void*)&out };
        launch_pdl((void*)se_scale_kernel, dim3(PLANES), dim3(TPB), args);
    }
}